// round 3
// baseline (speedup 1.0000x reference)
#include <cuda_runtime.h>
#include <cuda_bf16.h>
#include <cstdint>

// MatrixExpander: out(16,16,512,512) = kron(A(16,16,64,64), ones(8,8)), fp32.
//
// Tile c in [0,16384): output span out + c*4096 floats (16 KB contiguous)
// = 8 identical copies of the expanded A-row (512 floats, 2 KB), where
// expanded[j] = A[c*64 + j/8].
//
// R3 design: one WARP per tile. Warp builds the 2 KB expanded row once in
// SMEM (32 lanes x 4 STS.128), then lane 0 issues EIGHT 2 KB 1D TMA bulk
// stores from that same SMEM source to the 8 consecutive output rows.
// - STS traffic cut 8x vs R2 (was the 65%-busy L1 path)
// - no __syncthreads; 8 independent warp pipelines per CTA
// - 2 buffers/warp, 2 tiles/warp, waits deferred to kernel end -> TMA
//   stores from all warps stay in flight (deep store MLP, no CTA churn)

__device__ __forceinline__ uint32_t smem_u32(const void* p) {
    uint32_t a;
    asm("{ .reg .u64 t; cvta.to.shared.u64 t, %1; cvt.u32.u64 %0, t; }"
        : "=r"(a) : "l"(p));
    return a;
}

static constexpr uint32_t NTILES = 16384;   // 16*16*64

__global__ __launch_bounds__(256)
void expander_warp_tma_kernel(const float* __restrict__ A, float* __restrict__ out)
{
    // 8 warps x 2 buffers x 128 float4 (2 KB) = 32 KB
    __shared__ __align__(128) float4 buf[8][2][128];

    const uint32_t wid    = threadIdx.x >> 5;
    const uint32_t lane   = threadIdx.x & 31u;
    const uint32_t gwarp  = (blockIdx.x << 3) | wid;
    const uint32_t nwarps = gridDim.x << 3;

    uint32_t it = 0;
    for (uint32_t c = gwarp; c < NTILES; c += nwarps, ++it) {
        // Start the A-row load early (doesn't touch smem).
        // Lane l produces float4 slots 4l..4l+3; slot f covers A col f>>1,
        // so lane l needs A cols 2l and 2l+1 -> one float2.
        const float2 av = *reinterpret_cast<const float2*>(
            A + (c << 6) + (lane << 1));

        // Backpressure before reusing a buffer (never binds with 2 tiles/warp,
        // kept for grid-shape robustness).
        if (it >= 2) {
            if (lane == 0)
                asm volatile("cp.async.bulk.wait_group.read 1;" ::: "memory");
            __syncwarp();
        }

        float4* b = buf[wid][it & 1u];
        const float4 v0 = make_float4(av.x, av.x, av.x, av.x);
        const float4 v1 = make_float4(av.y, av.y, av.y, av.y);
        b[(lane << 2) + 0] = v0;
        b[(lane << 2) + 1] = v0;
        b[(lane << 2) + 2] = v1;
        b[(lane << 2) + 3] = v1;
        __syncwarp();

        if (lane == 0) {
            asm volatile("fence.proxy.async.shared::cta;" ::: "memory");
            const uint32_t s = smem_u32(b);
            float* dst = out + ((size_t)c << 12);
            #pragma unroll
            for (int r = 0; r < 8; ++r) {
                asm volatile(
                    "cp.async.bulk.global.shared::cta.bulk_group [%0], [%1], %2;"
                    :: "l"(dst + (r << 9)), "r"(s), "n"(2048) : "memory");
            }
            asm volatile("cp.async.bulk.commit_group;" ::: "memory");
        }
        __syncwarp();
    }

    // Drain this thread's bulk groups before exit (lane 0 owns them all).
    if (lane == 0)
        asm volatile("cp.async.bulk.wait_group 0;" ::: "memory");
}

extern "C" void kernel_launch(void* const* d_in, const int* in_sizes, int n_in,
                              void* d_out, int out_size)
{
    const float* A = (const float*)d_in[0];   // (16,16,64,64) fp32
    float* out = (float*)d_out;               // (16,16,512,512) fp32

    // 1024 CTAs x 8 warps = 8192 warps -> exactly 2 tiles per warp.
    expander_warp_tma_kernel<<<1024, 256>>>(A, out);
}